// round 13
// baseline (speedup 1.0000x reference)
#include <cuda_runtime.h>

#define MAXN 100000
#define DFEAT 64

// Scratch (allocation-free): message accumulator, degree, hidden layer output.
__device__ __align__(16) float g_msg[MAXN * DFEAT];
__device__ __align__(16) float g_deg[MAXN];
__device__ __align__(16) float g_h[MAXN * DFEAT];

__device__ __forceinline__ void ffma2(unsigned long long& acc,
                                      unsigned long long a,
                                      unsigned long long b) {
    asm("fma.rn.f32x2 %0, %1, %2, %0;" : "+l"(acc) : "l"(a), "l"(b));
}

// ---------------------------------------------------------------------------
// Zeroing kernel (graph memset nodes reject __device__ symbol memory).
// ---------------------------------------------------------------------------
__global__ void zero_kernel(float4* __restrict__ msg, float* __restrict__ deg,
                            int n4, int ndeg) {
    int i = blockIdx.x * blockDim.x + threadIdx.x;
    if (i < n4) msg[i] = make_float4(0.f, 0.f, 0.f, 0.f);
    if (deg != nullptr && i < ndeg) deg[i] = 0.f;
}

// ---------------------------------------------------------------------------
// Scatter: for each edge (s -> d), msg[d] += feat[s]; optionally deg[d] += 1.
// 16 threads per edge, one float4 vector atomic each. Indices loaded once per
// 16-lane group (lanes 0/16) and broadcast via shfl.
// ---------------------------------------------------------------------------
__global__ void scatter_kernel(const float* __restrict__ feat,
                               const int* __restrict__ src,
                               const int* __restrict__ dst,
                               float* __restrict__ msg,
                               float* __restrict__ deg,
                               int E) {
    int tid = blockIdx.x * blockDim.x + threadIdx.x;
    int e = tid >> 4;
    int lane = threadIdx.x & 31;
    int c = lane & 15;
    bool valid = (e < E);
    int s = 0, d = 0;
    if (valid && c == 0) { s = src[e]; d = dst[e]; }
    s = __shfl_sync(0xffffffffu, s, lane & 16);
    d = __shfl_sync(0xffffffffu, d, lane & 16);
    if (!valid) return;
    float4 v = reinterpret_cast<const float4*>(feat)[s * 16 + c];
    atomicAdd(reinterpret_cast<float4*>(msg) + d * 16 + c, v);
    if (deg != nullptr && c == 0) atomicAdd(deg + d, 1.0f);
}

// ---------------------------------------------------------------------------
// Fused SAGE layer: out = (msg/max(deg,1)) @ Wl + bl + xin @ Wr
//   RELU   : apply relu, store hidden [N,64]
//   CLS    : fuse classifier out2 = h2 @ Wc + bc  [N,2] (h2 never stored)
//   ZEROMSG: zero this block's 32 msg rows after consuming them (replaces
//            the second zero_kernel)
// Block: 256 threads, 32 node-rows. Dynamic smem 50176B:
//   sA[32*64] | sX[32*64] | sWlT[64*66] | sWrT[64*66]   (weights TRANSPOSED)
// Mainloop uses fma.rn.f32x2 packed over even/odd k: A-pairs come free from
// float4 row loads; W-pairs come free from the transposed [c][k] layout.
// ---------------------------------------------------------------------------
template <bool RELU, bool CLS, bool ZEROMSG>
__global__ __launch_bounds__(256) void layer_kernel(
    const float* __restrict__ msg, const float* __restrict__ deg,
    const float* __restrict__ xin,
    const float* __restrict__ Wl, const float* __restrict__ bl,
    const float* __restrict__ Wr,
    const float* __restrict__ Wc, const float* __restrict__ bc,
    float* __restrict__ hout, float* __restrict__ out2,
    float* __restrict__ msgz, int N)
{
    extern __shared__ float smem[];
    float* sA   = smem;               // 2048 floats
    float* sX   = smem + 2048;        // 2048 floats
    float* sWlT = smem + 4096;        // 64*66 = 4224 floats
    float* sWrT = smem + 8320;        // 4224 floats

    int tid = threadIdx.x;
    int rowbase = blockIdx.x * 32;

    // Transposed weight load: sWT[c*66 + k] = W[k*64 + c].
    for (int i4 = tid; i4 < 1024; i4 += 256) {
        int k = i4 >> 4;
        int cb = (i4 & 15) * 4;
        float4 vl = reinterpret_cast<const float4*>(Wl)[i4];
        float4 vr = reinterpret_cast<const float4*>(Wr)[i4];
        sWlT[(cb + 0) * 66 + k] = vl.x; sWlT[(cb + 1) * 66 + k] = vl.y;
        sWlT[(cb + 2) * 66 + k] = vl.z; sWlT[(cb + 3) * 66 + k] = vl.w;
        sWrT[(cb + 0) * 66 + k] = vr.x; sWrT[(cb + 1) * 66 + k] = vr.y;
        sWrT[(cb + 2) * 66 + k] = vr.z; sWrT[(cb + 3) * 66 + k] = vr.w;
    }

    // Activation tiles; scale msg by 1/max(deg,1) on the way in.
    for (int i = tid; i < 512; i += 256) {
        int r = i >> 4;
        int row = rowbase + r;
        if (row >= N) row = N - 1;
        int g = row * 16 + (i & 15);
        float4 a = reinterpret_cast<const float4*>(msg)[g];
        float inv = 1.0f / fmaxf(deg[row], 1.0f);
        a.x *= inv; a.y *= inv; a.z *= inv; a.w *= inv;
        reinterpret_cast<float4*>(sA)[i] = a;
        reinterpret_cast<float4*>(sX)[i] = reinterpret_cast<const float4*>(xin)[g];
    }
    __syncthreads();

    // msg rows consumed -> zero them for the next scatter (overlaps mainloop).
    if (ZEROMSG) {
        float4 z4 = make_float4(0.f, 0.f, 0.f, 0.f);
        for (int i = tid; i < 512; i += 256) {
            int row = rowbase + (i >> 4);
            if (row < N)
                reinterpret_cast<float4*>(msgz)[row * 16 + (i & 15)] = z4;
        }
    }

    int tx = tid & 31;        // lane -> output columns tx, tx+32
    int ty = tid >> 5;        // warp -> rows ty*4 .. ty*4+3
    int c0 = tx, c1 = tx + 32;
    int ty4 = ty * 4;

    // acc[rr][cc]: f32x2 (even-k partial in lo, odd-k partial in hi)
    unsigned long long acc[4][2];
#pragma unroll
    for (int rr = 0; rr < 4; rr++) { acc[rr][0] = 0ull; acc[rr][1] = 0ull; }

#pragma unroll
    for (int k4 = 0; k4 < 64; k4 += 4) {
        ulonglong2 av[4], xv[4];
#pragma unroll
        for (int rr = 0; rr < 4; rr++) {
            av[rr] = *reinterpret_cast<const ulonglong2*>(&sA[(ty4 + rr) * 64 + k4]);
            xv[rr] = *reinterpret_cast<const ulonglong2*>(&sX[(ty4 + rr) * 64 + k4]);
        }
#pragma unroll
        for (int p = 0; p < 2; p++) {
            int k = k4 + 2 * p;
            unsigned long long wl0 = *reinterpret_cast<const unsigned long long*>(&sWlT[c0 * 66 + k]);
            unsigned long long wl1 = *reinterpret_cast<const unsigned long long*>(&sWlT[c1 * 66 + k]);
            unsigned long long wr0 = *reinterpret_cast<const unsigned long long*>(&sWrT[c0 * 66 + k]);
            unsigned long long wr1 = *reinterpret_cast<const unsigned long long*>(&sWrT[c1 * 66 + k]);
#pragma unroll
            for (int rr = 0; rr < 4; rr++) {
                unsigned long long a = p ? av[rr].y : av[rr].x;
                unsigned long long x2 = p ? xv[rr].y : xv[rr].x;
                ffma2(acc[rr][0], a, wl0);
                ffma2(acc[rr][0], x2, wr0);
                ffma2(acc[rr][1], a, wl1);
                ffma2(acc[rr][1], x2, wr1);
            }
        }
    }

    float bias0 = bl[c0], bias1 = bl[c1];
    float h0[4], h1[4];
#pragma unroll
    for (int rr = 0; rr < 4; rr++) {
        float lo, hi;
        asm("mov.b64 {%0, %1}, %2;" : "=f"(lo), "=f"(hi) : "l"(acc[rr][0]));
        h0[rr] = lo + hi + bias0;
        asm("mov.b64 {%0, %1}, %2;" : "=f"(lo), "=f"(hi) : "l"(acc[rr][1]));
        h1[rr] = lo + hi + bias1;
    }

    if (RELU) {
#pragma unroll
        for (int rr = 0; rr < 4; rr++) {
            int row = rowbase + ty4 + rr;
            if (row < N) {
                hout[row * 64 + c0] = fmaxf(h0[rr], 0.0f);
                hout[row * 64 + c1] = fmaxf(h1[rr], 0.0f);
            }
        }
    }
    if (CLS) {
        float wc00 = Wc[c0 * 2 + 0], wc01 = Wc[c0 * 2 + 1];
        float wc10 = Wc[c1 * 2 + 0], wc11 = Wc[c1 * 2 + 1];
#pragma unroll
        for (int rr = 0; rr < 4; rr++) {
            float p0 = h0[rr] * wc00 + h1[rr] * wc10;
            float p1 = h0[rr] * wc01 + h1[rr] * wc11;
#pragma unroll
            for (int off = 16; off > 0; off >>= 1) {
                p0 += __shfl_down_sync(0xffffffffu, p0, off);
                p1 += __shfl_down_sync(0xffffffffu, p1, off);
            }
            if (tx == 0) {
                int row = rowbase + ty4 + rr;
                if (row < N) {
                    out2[row * 2 + 0] = p0 + bc[0];
                    out2[row * 2 + 1] = p1 + bc[1];
                }
            }
        }
    }
}

extern "C" void kernel_launch(void* const* d_in, const int* in_sizes, int n_in,
                              void* d_out, int out_size) {
    const float* x   = (const float*)d_in[0];
    const int*   ei  = (const int*)d_in[1];     // int32 (JAX x64-disabled)
    const float* W1l = (const float*)d_in[2];
    const float* b1  = (const float*)d_in[3];
    const float* W1r = (const float*)d_in[4];
    const float* W2l = (const float*)d_in[5];
    const float* b2  = (const float*)d_in[6];
    const float* W2r = (const float*)d_in[7];
    const float* Wc  = (const float*)d_in[8];
    const float* bc  = (const float*)d_in[9];
    float*       out = (float*)d_out;

    int N = in_sizes[0] / DFEAT;
    int E = in_sizes[1] / 2;
    const int* src = ei;
    const int* dst = ei + E;

    float *msg, *deg, *h;
    cudaGetSymbolAddress((void**)&msg, g_msg);
    cudaGetSymbolAddress((void**)&deg, g_deg);
    cudaGetSymbolAddress((void**)&h,   g_h);

    const int SMEM = 50176;  // (2048+2048+4224+4224) floats * 4B
    cudaFuncSetAttribute(layer_kernel<true, false, true>,
                         cudaFuncAttributeMaxDynamicSharedMemorySize, SMEM);
    cudaFuncSetAttribute(layer_kernel<false, true, false>,
                         cudaFuncAttributeMaxDynamicSharedMemorySize, SMEM);

    int n4 = N * DFEAT / 4;
    int zgrid = (n4 + 255) / 256;
    int sgrid = (int)(((long long)E * 16 + 255) / 256);
    int lgrid = (N + 31) / 32;

    // Layer 1
    zero_kernel<<<zgrid, 256>>>((float4*)msg, deg, n4, N);
    scatter_kernel<<<sgrid, 256>>>(x, src, dst, msg, deg, E);
    layer_kernel<true, false, true><<<lgrid, 256, SMEM>>>(
        msg, deg, x, W1l, b1, W1r, nullptr, nullptr, h, nullptr, msg, N);
    // Layer 2 (+ fused classifier); msg already re-zeroed by layer 1, deg reused.
    scatter_kernel<<<sgrid, 256>>>(h, src, dst, msg, nullptr, E);
    layer_kernel<false, true, false><<<lgrid, 256, SMEM>>>(
        msg, deg, h, W2l, b2, W2r, Wc, bc, nullptr, out, nullptr, N);
}